// round 1
// baseline (speedup 1.0000x reference)
#include <cuda_runtime.h>

#define N_NODES 50000
#define C_IN    256
#define C_OUT   256
#define D_DOM   25000
#define K_DOM   16

// ---------------- scratch (static device globals; no cudaMalloc allowed) ---
__device__ float g_weff[C_IN * C_OUT];                    // 256 KB
__device__ float g_z[(size_t)N_NODES * C_OUT];            // 51.2 MB
__device__ int   g_dom_is32;                              // 1 if domains is int32

// ---------------- kernel 1: fold the concat into one weight matrix ---------
// weff[c,o] = w[c,o] + w[c+C_IN,o]
__global__ void weff_kernel(const float* __restrict__ w) {
    int i = blockIdx.x * blockDim.x + threadIdx.x;
    if (i < C_IN * C_OUT)
        g_weff[i] = w[i] + w[i + C_IN * C_OUT];
}

// ---------------- kernel 2: detect domains dtype (int64 vs int32) ----------
// If the buffer actually holds int32 indices, reading it as int64 combines two
// random indices -> values far outside [0, N). Scan a prefix and set a flag.
__global__ void detect_dom_kernel(const long long* __restrict__ dom) {
    int bad = 0;
    for (int i = threadIdx.x; i < 2048; i += 256) {
        long long v = dom[i];
        if (v < 0 || v >= (long long)N_NODES) bad = 1;
    }
    bad = __syncthreads_or(bad);
    if (threadIdx.x == 0) g_dom_is32 = bad;
}

// ---------------- kernel 3: z = (x * sn) @ weff + b ------------------------
// Classic 128x128x8 fp32 SGEMM, 256 threads, 8x8 per thread.
__global__ __launch_bounds__(256, 2)
void zgemm_kernel(const float* __restrict__ x,
                  const float* __restrict__ sn,
                  const float* __restrict__ bias) {
    __shared__ float As[8][128];
    __shared__ float Bs[8][128];

    const int tid = threadIdx.x;
    const int m0 = blockIdx.y * 128;
    const int n0 = blockIdx.x * 128;

    // A-tile loader mapping: one float4 per thread (128 rows x 8 cols)
    const int arow = tid >> 1;           // 0..127
    const int acol = (tid & 1) * 4;      // 0 or 4
    // B-tile loader mapping: one float4 per thread (8 rows x 128 cols)
    const int brow = tid >> 5;           // 0..7
    const int bcol = (tid & 31) * 4;     // 0..124

    const int gm_a = m0 + arow;
    const bool a_ok = (gm_a < N_NODES);
    const float sn_a = a_ok ? sn[gm_a] : 0.0f;
    const float* xrow = x + (size_t)gm_a * C_IN;

    const int ty = tid >> 4;             // 0..15  (row group)
    const int tx = tid & 15;             // 0..15  (col group)

    float acc[8][8];
#pragma unroll
    for (int i = 0; i < 8; i++)
#pragma unroll
        for (int j = 0; j < 8; j++) acc[i][j] = 0.0f;

    for (int k0 = 0; k0 < C_IN; k0 += 8) {
        // load A (apply symmetric normalization inline), store transposed
        float4 av = make_float4(0.f, 0.f, 0.f, 0.f);
        if (a_ok) av = *(const float4*)(xrow + k0 + acol);
        As[acol + 0][arow] = av.x * sn_a;
        As[acol + 1][arow] = av.y * sn_a;
        As[acol + 2][arow] = av.z * sn_a;
        As[acol + 3][arow] = av.w * sn_a;
        // load B
        *(float4*)(&Bs[brow][bcol]) =
            *(const float4*)(g_weff + (k0 + brow) * C_OUT + n0 + bcol);
        __syncthreads();

#pragma unroll
        for (int k = 0; k < 8; k++) {
            float a[8], b[8];
            *(float4*)(a)     = *(const float4*)(&As[k][ty * 8]);
            *(float4*)(a + 4) = *(const float4*)(&As[k][ty * 8 + 4]);
            *(float4*)(b)     = *(const float4*)(&Bs[k][tx * 8]);
            *(float4*)(b + 4) = *(const float4*)(&Bs[k][tx * 8 + 4]);
#pragma unroll
            for (int i = 0; i < 8; i++)
#pragma unroll
                for (int j = 0; j < 8; j++)
                    acc[i][j] = fmaf(a[i], b[j], acc[i][j]);
        }
        __syncthreads();
    }

    // epilogue: add bias, store z
    const float4 b0 = *(const float4*)(bias + n0 + tx * 8);
    const float4 b1 = *(const float4*)(bias + n0 + tx * 8 + 4);
#pragma unroll
    for (int i = 0; i < 8; i++) {
        int gm = m0 + ty * 8 + i;
        if (gm < N_NODES) {
            float* zr = g_z + (size_t)gm * C_OUT + n0 + tx * 8;
            float4 v0, v1;
            v0.x = acc[i][0] + b0.x; v0.y = acc[i][1] + b0.y;
            v0.z = acc[i][2] + b0.z; v0.w = acc[i][3] + b0.w;
            v1.x = acc[i][4] + b1.x; v1.y = acc[i][5] + b1.y;
            v1.z = acc[i][6] + b1.z; v1.w = acc[i][7] + b1.w;
            *(float4*)(zr)     = v0;
            *(float4*)(zr + 4) = v1;
        }
    }
}

// ---------------- kernel 4: gather rows of z into the output ---------------
// out[row, :] = z[domains[row], :], row in [0, D*K), 256 floats = 64 float4.
__global__ __launch_bounds__(256)
void gather_kernel(const void* __restrict__ domains, float4* __restrict__ out) {
    const int idx = blockIdx.x * 256 + threadIdx.x;   // total = D*K*64 exactly
    const int row = idx >> 6;
    const int q   = idx & 63;
    long long dom;
    if (g_dom_is32) dom = ((const int*)domains)[row];
    else            dom = ((const long long*)domains)[row];
    const float4* src = (const float4*)(g_z + (size_t)dom * C_OUT);
    out[idx] = src[q];
}

// ---------------- launch ---------------------------------------------------
extern "C" void kernel_launch(void* const* d_in, const int* in_sizes, int n_in,
                              void* d_out, int out_size) {
    const float*     x   = (const float*)d_in[0];
    const float*     sn  = (const float*)d_in[1];
    const void*      dom = d_in[2];
    const float*     w   = (const float*)d_in[3];
    const float*     b   = (const float*)d_in[4];

    weff_kernel<<<(C_IN * C_OUT + 255) / 256, 256>>>(w);
    detect_dom_kernel<<<1, 256>>>((const long long*)dom);

    dim3 ggrid(C_OUT / 128, (N_NODES + 127) / 128);
    zgemm_kernel<<<ggrid, 256>>>(x, sn, b);

    const int total4 = D_DOM * K_DOM * (C_OUT / 4);   // 25,600,000
    gather_kernel<<<total4 / 256, 256>>>(dom, (float4*)d_out);
}

// round 3
// speedup vs baseline: 1.5827x; 1.5827x over previous
#include <cuda_runtime.h>
#include <cuda_bf16.h>
#include <cstdint>

#define N_NODES 50000
#define C_IN    256
#define C_OUT   256
#define D_DOM   25000
#define K_DOM   16

#define BM      128
#define BN      128
#define NCHUNK  16            // 16 K-chunks of 16 = K 256
#define NSTAGES 4
#define STAGE_BYTES 16384     // Ahi/Alo/Bhi/Blo, 4KB each
#define SM_A_HI 0
#define SM_A_LO 4096
#define SM_B_HI 8192
#define SM_B_LO 12288
#define M_TILES ((N_NODES + BM - 1) / BM)    // 391

// ---------------- scratch (static device globals; no cudaMalloc) -----------
__device__ __align__(16) float          g_z[(size_t)N_NODES * C_OUT];   // 51.2MB
__device__ __align__(16) __nv_bfloat16  g_wt_hi[C_OUT * C_IN];          // B^T hi
__device__ __align__(16) __nv_bfloat16  g_wt_lo[C_OUT * C_IN];          // B^T lo
__device__ __align__(16) __nv_bfloat16  g_a_hi[(size_t)N_NODES * C_IN]; // 25.6MB
__device__ __align__(16) __nv_bfloat16  g_a_lo[(size_t)N_NODES * C_IN]; // 25.6MB
__device__ int g_dom_is32;

// ---------------- helpers ---------------------------------------------------
__device__ __forceinline__ uint32_t smem_u32(const void* p) {
    uint32_t a;
    asm("{ .reg .u64 t; cvta.to.shared.u64 t, %1; cvt.u32.u64 %0, t; }"
        : "=r"(a) : "l"(p));
    return a;
}

__device__ __forceinline__ void cp16(uint32_t dst, const void* src, int sz) {
    asm volatile("cp.async.cg.shared.global [%0], [%1], 16, %2;"
                 :: "r"(dst), "l"(src), "r"(sz) : "memory");
}

#define CP_COMMIT() asm volatile("cp.async.commit_group;" ::: "memory")
#define CP_WAIT2()  asm volatile("cp.async.wait_group 2;" ::: "memory")

#define LDM4(r0, r1, r2, r3, addr) \
    asm volatile("ldmatrix.sync.aligned.m8n8.x4.shared.b16 {%0,%1,%2,%3}, [%4];" \
                 : "=r"(r0), "=r"(r1), "=r"(r2), "=r"(r3) : "r"(addr))

#define MMA16816(d, a, b) \
    asm volatile("mma.sync.aligned.m16n8k16.row.col.f32.bf16.bf16.f32 " \
                 "{%0,%1,%2,%3}, {%4,%5,%6,%7}, {%8,%9}, {%0,%1,%2,%3};" \
                 : "+f"((d)[0]), "+f"((d)[1]), "+f"((d)[2]), "+f"((d)[3]) \
                 : "r"((a)[0]), "r"((a)[1]), "r"((a)[2]), "r"((a)[3]), \
                   "r"((b)[0]), "r"((b)[1]))

__device__ __forceinline__ uint32_t pack_bf16(float a, float b) {
    __nv_bfloat16 ha = __float2bfloat16(a);
    __nv_bfloat16 hb = __float2bfloat16(b);
    return ((uint32_t)__bfloat16_as_ushort(hb) << 16) | __bfloat16_as_ushort(ha);
}

// ---------------- kernel 1: weff^T = (w0+w1)^T, split hi/lo bf16 -----------
__global__ void prep_w_kernel(const float* __restrict__ w) {
    int i = blockIdx.x * blockDim.x + threadIdx.x;
    if (i < C_IN * C_OUT) {
        int n = i & (C_OUT - 1);
        int k = i >> 8;
        float v = w[k * C_OUT + n] + w[(k + C_IN) * C_OUT + n];
        __nv_bfloat16 h = __float2bfloat16(v);
        g_wt_hi[n * C_IN + k] = h;
        g_wt_lo[n * C_IN + k] = __float2bfloat16(v - __bfloat162float(h));
    }
}

// ---------------- kernel 2: A = x * sn, split hi/lo bf16 -------------------
__global__ __launch_bounds__(256)
void prep_a_kernel(const float* __restrict__ x, const float* __restrict__ sn) {
    int idx = blockIdx.x * 256 + threadIdx.x;        // 0 .. N*64-1
    if (idx >= N_NODES * 64) return;
    int row = idx >> 6;
    int c4  = idx & 63;
    float s = sn[row];
    float4 v = *(const float4*)(x + (size_t)row * C_IN + c4 * 4);
    v.x *= s; v.y *= s; v.z *= s; v.w *= s;
    __nv_bfloat16 h0 = __float2bfloat16(v.x);
    __nv_bfloat16 h1 = __float2bfloat16(v.y);
    __nv_bfloat16 h2 = __float2bfloat16(v.z);
    __nv_bfloat16 h3 = __float2bfloat16(v.w);
    uint2 hi, lo;
    hi.x = ((uint32_t)__bfloat16_as_ushort(h1) << 16) | __bfloat16_as_ushort(h0);
    hi.y = ((uint32_t)__bfloat16_as_ushort(h3) << 16) | __bfloat16_as_ushort(h2);
    lo.x = pack_bf16(v.x - __bfloat162float(h0), v.y - __bfloat162float(h1));
    lo.y = pack_bf16(v.z - __bfloat162float(h2), v.w - __bfloat162float(h3));
    *(uint2*)(g_a_hi + (size_t)row * C_IN + c4 * 4) = hi;
    *(uint2*)(g_a_lo + (size_t)row * C_IN + c4 * 4) = lo;
}

// ---------------- kernel 3: detect domains dtype ---------------------------
__global__ void detect_dom_kernel(const long long* __restrict__ dom) {
    int bad = 0;
    for (int i = threadIdx.x; i < 2048; i += 256) {
        long long v = dom[i];
        if (v < 0 || v >= (long long)N_NODES) bad = 1;
    }
    bad = __syncthreads_or(bad);
    if (threadIdx.x == 0) g_dom_is32 = bad;
}

// ---------------- kernel 4: z = A @ weff + b via mma.sync bf16-split -------
extern __shared__ char dsm[];

__global__ __launch_bounds__(256)
void zgemm_mma_kernel(const float* __restrict__ bias) {
    const int tid = threadIdx.x;
    const int m0 = (blockIdx.x >> 1) * BM;
    const int n0 = (blockIdx.x & 1) * BN;
    const uint32_t sb = smem_u32(dsm);

    // --- copy-role mapping: one 16B per thread per matrix per stage --------
    const int crow = tid >> 1;          // 0..127
    const int cseg = tid & 1;           // 16B segment within 32B row
    const int gmA  = m0 + crow;
    const int szA  = (gmA < N_NODES) ? 16 : 0;     // zfill tail rows
    const char* srcAhi = (const char*)(g_a_hi + (size_t)gmA * C_IN + cseg * 8);
    const char* srcAlo = (const char*)(g_a_lo + (size_t)gmA * C_IN + cseg * 8);
    const char* srcBhi = (const char*)(g_wt_hi + (size_t)(n0 + crow) * C_IN + cseg * 8);
    const char* srcBlo = (const char*)(g_wt_lo + (size_t)(n0 + crow) * C_IN + cseg * 8);
    const uint32_t doff = crow * 32 + cseg * 16;

#define ISSUE_COPY(s, kc) do {                                   \
        uint32_t _sbase = sb + (uint32_t)(s) * STAGE_BYTES;      \
        int _go = (kc) * 32;                                     \
        cp16(_sbase + SM_A_HI + doff, srcAhi + _go, szA);        \
        cp16(_sbase + SM_A_LO + doff, srcAlo + _go, szA);        \
        cp16(_sbase + SM_B_HI + doff, srcBhi + _go, 16);         \
        cp16(_sbase + SM_B_LO + doff, srcBlo + _go, 16);         \
    } while (0)

    // --- prologue: fill NSTAGES-1 stages -----------------------------------
    ISSUE_COPY(0, 0); CP_COMMIT();
    ISSUE_COPY(1, 1); CP_COMMIT();
    ISSUE_COPY(2, 2); CP_COMMIT();

    // --- compute-role mapping ----------------------------------------------
    const int lane = tid & 31;
    const int wid  = tid >> 5;
    const int wm   = wid & 1;           // 2 warps along M  (64 rows each)
    const int wn   = wid >> 1;          // 4 warps along N  (32 cols each)
    const int lrow  = lane & 15;
    const int lhalf = lane >> 4;
    const uint32_t a_off = (uint32_t)(wm * 64 + lrow) * 32 + lhalf * 16;
    const uint32_t b_off = (uint32_t)(wn * 32 + lrow) * 32 + lhalf * 16;

    float acc[4][4][4];
#pragma unroll
    for (int mt = 0; mt < 4; mt++)
#pragma unroll
        for (int nt = 0; nt < 4; nt++)
#pragma unroll
            for (int j = 0; j < 4; j++) acc[mt][nt][j] = 0.0f;

    for (int kc = 0; kc < NCHUNK; kc++) {
        CP_WAIT2();                     // NSTAGES-2: stage kc ready
        __syncthreads();                // also: all warps done with stage kc-1
        int pf = kc + NSTAGES - 1;
        if (pf < NCHUNK) ISSUE_COPY(pf & (NSTAGES - 1), pf);
        CP_COMMIT();

        const uint32_t st = sb + (uint32_t)(kc & (NSTAGES - 1)) * STAGE_BYTES;

        uint32_t ah[4][4], bh[4][2], bl[4][2];
#pragma unroll
        for (int mt = 0; mt < 4; mt++)
            LDM4(ah[mt][0], ah[mt][1], ah[mt][2], ah[mt][3],
                 st + SM_A_HI + a_off + mt * 512);
#pragma unroll
        for (int ntp = 0; ntp < 2; ntp++) {
            uint32_t r0, r1, r2, r3;
            LDM4(r0, r1, r2, r3, st + SM_B_HI + b_off + ntp * 512);
            bh[ntp * 2][0] = r0; bh[ntp * 2][1] = r2;
            bh[ntp * 2 + 1][0] = r1; bh[ntp * 2 + 1][1] = r3;
            LDM4(r0, r1, r2, r3, st + SM_B_LO + b_off + ntp * 512);
            bl[ntp * 2][0] = r0; bl[ntp * 2][1] = r2;
            bl[ntp * 2 + 1][0] = r1; bl[ntp * 2 + 1][1] = r3;
        }
        // hi*hi + hi*lo
#pragma unroll
        for (int mt = 0; mt < 4; mt++)
#pragma unroll
            for (int nt = 0; nt < 4; nt++) {
                MMA16816(acc[mt][nt], ah[mt], bh[nt]);
                MMA16816(acc[mt][nt], ah[mt], bl[nt]);
            }
        // lo*hi (reuse ah registers for A-lo)
#pragma unroll
        for (int mt = 0; mt < 4; mt++)
            LDM4(ah[mt][0], ah[mt][1], ah[mt][2], ah[mt][3],
                 st + SM_A_LO + a_off + mt * 512);
#pragma unroll
        for (int mt = 0; mt < 4; mt++)
#pragma unroll
            for (int nt = 0; nt < 4; nt++)
                MMA16816(acc[mt][nt], ah[mt], bh[nt]);
    }

    // --- epilogue: bias + store to g_z -------------------------------------
    const int erow = lane >> 2;         // 0..7
    const int ecol = (lane & 3) * 2;
#pragma unroll
    for (int nt = 0; nt < 4; nt++) {
        int n = n0 + wn * 32 + nt * 8 + ecol;
        float b0v = bias[n];
        float b1v = bias[n + 1];
#pragma unroll
        for (int mt = 0; mt < 4; mt++) {
            int m = m0 + wm * 64 + mt * 16 + erow;
            if (m < N_NODES)
                *(float2*)(g_z + (size_t)m * C_OUT + n) =
                    make_float2(acc[mt][nt][0] + b0v, acc[mt][nt][1] + b1v);
            if (m + 8 < N_NODES)
                *(float2*)(g_z + (size_t)(m + 8) * C_OUT + n) =
                    make_float2(acc[mt][nt][2] + b0v, acc[mt][nt][3] + b1v);
        }
    }
#undef ISSUE_COPY
}

// ---------------- kernel 5: gather, MLP=4 per thread -----------------------
__global__ __launch_bounds__(256)
void gather_kernel(const void* __restrict__ domains, float4* __restrict__ out) {
    const int q    = threadIdx.x & 63;
    const int rg   = threadIdx.x >> 6;
    const int row0 = blockIdx.x * 16 + rg * 4;
    int i0, i1, i2, i3;
    if (g_dom_is32) {
        const int* d = (const int*)domains;
        i0 = d[row0]; i1 = d[row0 + 1]; i2 = d[row0 + 2]; i3 = d[row0 + 3];
    } else {
        const long long* d = (const long long*)domains;
        i0 = (int)d[row0];     i1 = (int)d[row0 + 1];
        i2 = (int)d[row0 + 2]; i3 = (int)d[row0 + 3];
    }
    const float4* z4 = (const float4*)g_z;
    float4 v0 = z4[(size_t)i0 * 64 + q];
    float4 v1 = z4[(size_t)i1 * 64 + q];
    float4 v2 = z4[(size_t)i2 * 64 + q];
    float4 v3 = z4[(size_t)i3 * 64 + q];
    out[(size_t)(row0 + 0) * 64 + q] = v0;
    out[(size_t)(row0 + 1) * 64 + q] = v1;
    out[(size_t)(row0 + 2) * 64 + q] = v2;
    out[(size_t)(row0 + 3) * 64 + q] = v3;
}

// ---------------- launch ---------------------------------------------------
extern "C" void kernel_launch(void* const* d_in, const int* in_sizes, int n_in,
                              void* d_out, int out_size) {
    const float* x   = (const float*)d_in[0];
    const float* sn  = (const float*)d_in[1];
    const void*  dom = d_in[2];
    const float* w   = (const float*)d_in[3];
    const float* b   = (const float*)d_in[4];

    cudaFuncSetAttribute(zgemm_mma_kernel,
                         cudaFuncAttributeMaxDynamicSharedMemorySize,
                         NSTAGES * STAGE_BYTES);

    prep_w_kernel<<<(C_IN * C_OUT + 255) / 256, 256>>>(w);
    prep_a_kernel<<<(N_NODES * 64 + 255) / 256, 256>>>(x, sn);
    detect_dom_kernel<<<1, 256>>>((const long long*)dom);

    zgemm_mma_kernel<<<M_TILES * 2, 256, NSTAGES * STAGE_BYTES>>>(b);

    gather_kernel<<<(D_DOM * K_DOM) / 16, 256>>>(dom, (float4*)d_out);
}

// round 4
// speedup vs baseline: 1.7050x; 1.0772x over previous
#include <cuda_runtime.h>
#include <cuda_bf16.h>
#include <cstdint>

#define N_NODES 50000
#define C_IN    256
#define C_OUT   256
#define D_DOM   25000
#define K_DOM   16

#define BM      128
#define BN      128
#define NCHUNK  16            // 16 K-chunks of 16 = K 256
#define NSTAGES 4
#define STAGE_BYTES 16384     // Ahi/Alo/Bhi/Blo, 4KB each
#define SM_A_HI 0
#define SM_A_LO 4096
#define SM_B_HI 8192
#define SM_B_LO 12288
#define M_TILES ((N_NODES + BM - 1) / BM)    // 391

// ---------------- scratch (static device globals; no cudaMalloc) -----------
__device__ __align__(16) float          g_z[(size_t)N_NODES * C_OUT];   // 51.2MB
__device__ __align__(16) __nv_bfloat16  g_wt_hi[C_OUT * C_IN];
__device__ __align__(16) __nv_bfloat16  g_wt_lo[C_OUT * C_IN];
__device__ __align__(16) __nv_bfloat16  g_a_hi[(size_t)N_NODES * C_IN]; // 25.6MB
__device__ __align__(16) __nv_bfloat16  g_a_lo[(size_t)N_NODES * C_IN]; // 25.6MB
__device__ int g_dom_is32;

// ---------------- helpers ---------------------------------------------------
__device__ __forceinline__ uint32_t smem_u32(const void* p) {
    uint32_t a;
    asm("{ .reg .u64 t; cvta.to.shared.u64 t, %1; cvt.u32.u64 %0, t; }"
        : "=r"(a) : "l"(p));
    return a;
}

__device__ __forceinline__ void cp16(uint32_t dst, const void* src, int sz) {
    asm volatile("cp.async.cg.shared.global [%0], [%1], 16, %2;"
                 :: "r"(dst), "l"(src), "r"(sz) : "memory");
}

#define CP_COMMIT() asm volatile("cp.async.commit_group;" ::: "memory")
#define CP_WAIT2()  asm volatile("cp.async.wait_group 2;" ::: "memory")

#define LDM4(r0, r1, r2, r3, addr) \
    asm volatile("ldmatrix.sync.aligned.m8n8.x4.shared.b16 {%0,%1,%2,%3}, [%4];" \
                 : "=r"(r0), "=r"(r1), "=r"(r2), "=r"(r3) : "r"(addr))

#define MMA16816(d, a, b) \
    asm volatile("mma.sync.aligned.m16n8k16.row.col.f32.bf16.bf16.f32 " \
                 "{%0,%1,%2,%3}, {%4,%5,%6,%7}, {%8,%9}, {%0,%1,%2,%3};" \
                 : "+f"((d)[0]), "+f"((d)[1]), "+f"((d)[2]), "+f"((d)[3]) \
                 : "r"((a)[0]), "r"((a)[1]), "r"((a)[2]), "r"((a)[3]), \
                   "r"((b)[0]), "r"((b)[1]))

__device__ __forceinline__ uint32_t pack_bf16(float a, float b) {
    __nv_bfloat16 ha = __float2bfloat16(a);
    __nv_bfloat16 hb = __float2bfloat16(b);
    return ((uint32_t)__bfloat16_as_ushort(hb) << 16) | __bfloat16_as_ushort(ha);
}

__device__ __forceinline__ void st_cs4(float4* p, float4 v) {
    asm volatile("st.global.cs.v4.f32 [%0], {%1,%2,%3,%4};"
                 :: "l"(p), "f"(v.x), "f"(v.y), "f"(v.z), "f"(v.w) : "memory");
}

// ---------------- kernel 1: weff^T = (w0+w1)^T, split hi/lo bf16 -----------
__global__ void prep_w_kernel(const float* __restrict__ w) {
    int i = blockIdx.x * blockDim.x + threadIdx.x;
    if (i < C_IN * C_OUT) {
        int n = i & (C_OUT - 1);
        int k = i >> 8;
        float v = w[k * C_OUT + n] + w[(k + C_IN) * C_OUT + n];
        __nv_bfloat16 h = __float2bfloat16(v);
        g_wt_hi[n * C_IN + k] = h;
        g_wt_lo[n * C_IN + k] = __float2bfloat16(v - __bfloat162float(h));
    }
}

// ---------------- kernel 2: A = x * sn, split hi/lo bf16 -------------------
__global__ __launch_bounds__(256)
void prep_a_kernel(const float* __restrict__ x, const float* __restrict__ sn) {
    int idx = blockIdx.x * 256 + threadIdx.x;        // 0 .. N*64-1
    if (idx >= N_NODES * 64) return;
    int row = idx >> 6;
    int c4  = idx & 63;
    float s = __ldg(sn + row);
    float4 v = *(const float4*)(x + (size_t)row * C_IN + c4 * 4);
    v.x *= s; v.y *= s; v.z *= s; v.w *= s;
    __nv_bfloat16 h0 = __float2bfloat16(v.x);
    __nv_bfloat16 h1 = __float2bfloat16(v.y);
    __nv_bfloat16 h2 = __float2bfloat16(v.z);
    __nv_bfloat16 h3 = __float2bfloat16(v.w);
    uint2 hi, lo;
    hi.x = ((uint32_t)__bfloat16_as_ushort(h1) << 16) | __bfloat16_as_ushort(h0);
    hi.y = ((uint32_t)__bfloat16_as_ushort(h3) << 16) | __bfloat16_as_ushort(h2);
    lo.x = pack_bf16(v.x - __bfloat162float(h0), v.y - __bfloat162float(h1));
    lo.y = pack_bf16(v.z - __bfloat162float(h2), v.w - __bfloat162float(h3));
    *(uint2*)(g_a_hi + (size_t)row * C_IN + c4 * 4) = hi;
    *(uint2*)(g_a_lo + (size_t)row * C_IN + c4 * 4) = lo;
}

// ---------------- kernel 3: detect domains dtype ---------------------------
__global__ void detect_dom_kernel(const long long* __restrict__ dom) {
    int bad = 0;
    for (int i = threadIdx.x; i < 2048; i += 256) {
        long long v = dom[i];
        if (v < 0 || v >= (long long)N_NODES) bad = 1;
    }
    bad = __syncthreads_or(bad);
    if (threadIdx.x == 0) g_dom_is32 = bad;
}

// ---------------- kernel 4: z = A @ weff + b via mma.sync bf16-split -------
// SMEM layout per 128-row tile: logical (row, seg16B) stored at
//   row*32 + (seg ^ ((row>>2)&1))*16        (conflict-free for ldmatrix.x4)
extern __shared__ char dsm[];

__global__ __launch_bounds__(256)
void zgemm_mma_kernel(const float* __restrict__ bias) {
    const int tid = threadIdx.x;
    const int m0 = (blockIdx.x >> 1) * BM;
    const int n0 = (blockIdx.x & 1) * BN;
    const uint32_t sb = smem_u32(dsm);

    // --- copy-role mapping: one 16B per thread per matrix per stage --------
    const int crow = tid >> 1;          // 0..127
    const int cseg = tid & 1;           // logical 16B segment within 32B row
    const int gmA  = m0 + crow;
    const int szA  = (gmA < N_NODES) ? 16 : 0;     // zfill tail rows
    const char* srcAhi = (const char*)(g_a_hi + (size_t)gmA * C_IN + cseg * 8);
    const char* srcAlo = (const char*)(g_a_lo + (size_t)gmA * C_IN + cseg * 8);
    const char* srcBhi = (const char*)(g_wt_hi + (size_t)(n0 + crow) * C_IN + cseg * 8);
    const char* srcBlo = (const char*)(g_wt_lo + (size_t)(n0 + crow) * C_IN + cseg * 8);
    const uint32_t doff = crow * 32 + (uint32_t)(cseg ^ ((crow >> 2) & 1)) * 16;

#define ISSUE_COPY(s, kc) do {                                   \
        uint32_t _sbase = sb + (uint32_t)(s) * STAGE_BYTES;      \
        int _go = (kc) * 32;                                     \
        cp16(_sbase + SM_A_HI + doff, srcAhi + _go, szA);        \
        cp16(_sbase + SM_A_LO + doff, srcAlo + _go, szA);        \
        cp16(_sbase + SM_B_HI + doff, srcBhi + _go, 16);         \
        cp16(_sbase + SM_B_LO + doff, srcBlo + _go, 16);         \
    } while (0)

    // --- prologue: fill NSTAGES-1 stages -----------------------------------
    ISSUE_COPY(0, 0); CP_COMMIT();
    ISSUE_COPY(1, 1); CP_COMMIT();
    ISSUE_COPY(2, 2); CP_COMMIT();

    // --- compute-role mapping ----------------------------------------------
    const int lane = tid & 31;
    const int wid  = tid >> 5;
    const int wm   = wid & 1;           // 2 warps along M  (64 rows each)
    const int wn   = wid >> 1;          // 4 warps along N  (32 cols each)
    const int lrow  = lane & 15;
    const int lhalf = lane >> 4;
    // swizzle bit depends only on (lrow>>2)&1 — all fragment offsets shift
    // row by multiples of 16, which leaves the bit unchanged.
    const int swz = (lrow >> 2) & 1;
    const uint32_t a_off = (uint32_t)(wm * 64 + lrow) * 32 + (uint32_t)(lhalf ^ swz) * 16;
    const uint32_t b_off = (uint32_t)(wn * 32 + lrow) * 32 + (uint32_t)(lhalf ^ swz) * 16;

    float acc[4][4][4];
#pragma unroll
    for (int mt = 0; mt < 4; mt++)
#pragma unroll
        for (int nt = 0; nt < 4; nt++)
#pragma unroll
            for (int j = 0; j < 4; j++) acc[mt][nt][j] = 0.0f;

    for (int kc = 0; kc < NCHUNK; kc++) {
        CP_WAIT2();                     // stage kc ready
        __syncthreads();
        int pf = kc + NSTAGES - 1;
        if (pf < NCHUNK) ISSUE_COPY(pf & (NSTAGES - 1), pf);
        CP_COMMIT();

        const uint32_t st = sb + (uint32_t)(kc & (NSTAGES - 1)) * STAGE_BYTES;

        uint32_t ah[4][4], bh[4][2], bl[4][2];
#pragma unroll
        for (int mt = 0; mt < 4; mt++)
            LDM4(ah[mt][0], ah[mt][1], ah[mt][2], ah[mt][3],
                 st + SM_A_HI + a_off + mt * 512);
#pragma unroll
        for (int ntp = 0; ntp < 2; ntp++) {
            uint32_t r0, r1, r2, r3;
            LDM4(r0, r1, r2, r3, st + SM_B_HI + b_off + ntp * 512);
            bh[ntp * 2][0] = r0; bh[ntp * 2][1] = r2;
            bh[ntp * 2 + 1][0] = r1; bh[ntp * 2 + 1][1] = r3;
            LDM4(r0, r1, r2, r3, st + SM_B_LO + b_off + ntp * 512);
            bl[ntp * 2][0] = r0; bl[ntp * 2][1] = r2;
            bl[ntp * 2 + 1][0] = r1; bl[ntp * 2 + 1][1] = r3;
        }
        // hi*hi + hi*lo
#pragma unroll
        for (int mt = 0; mt < 4; mt++)
#pragma unroll
            for (int nt = 0; nt < 4; nt++) {
                MMA16816(acc[mt][nt], ah[mt], bh[nt]);
                MMA16816(acc[mt][nt], ah[mt], bl[nt]);
            }
        // lo*hi (reuse ah registers for A-lo)
#pragma unroll
        for (int mt = 0; mt < 4; mt++)
            LDM4(ah[mt][0], ah[mt][1], ah[mt][2], ah[mt][3],
                 st + SM_A_LO + a_off + mt * 512);
#pragma unroll
        for (int mt = 0; mt < 4; mt++)
#pragma unroll
            for (int nt = 0; nt < 4; nt++)
                MMA16816(acc[mt][nt], ah[mt], bh[nt]);
    }

    // --- epilogue: bias + store to g_z -------------------------------------
    const int erow = lane >> 2;         // 0..7
    const int ecol = (lane & 3) * 2;
#pragma unroll
    for (int nt = 0; nt < 4; nt++) {
        int n = n0 + wn * 32 + nt * 8 + ecol;
        float b0v = bias[n];
        float b1v = bias[n + 1];
#pragma unroll
        for (int mt = 0; mt < 4; mt++) {
            int m = m0 + wm * 64 + mt * 16 + erow;
            if (m < N_NODES)
                *(float2*)(g_z + (size_t)m * C_OUT + n) =
                    make_float2(acc[mt][nt][0] + b0v, acc[mt][nt][1] + b1v);
            if (m + 8 < N_NODES)
                *(float2*)(g_z + (size_t)(m + 8) * C_OUT + n) =
                    make_float2(acc[mt][nt][2] + b0v, acc[mt][nt][3] + b1v);
        }
    }
#undef ISSUE_COPY
}

// ---------------- kernel 5: gather, MLP=8, streaming output stores ---------
// Block covers 32 output rows: thread t handles rows rg*8..rg*8+7 (rg=t>>6),
// float4 column q=t&63. Output uses st.cs (evict-first) so the 410MB write
// stream doesn't evict z (51MB, L2-resident) — z reads stay L2 hits.
__global__ __launch_bounds__(256)
void gather_kernel(const void* __restrict__ domains, float4* __restrict__ out) {
    const int q    = threadIdx.x & 63;
    const int rg   = threadIdx.x >> 6;
    const int row0 = blockIdx.x * 32 + rg * 8;
    int idx[8];
    if (g_dom_is32) {
        const int* d = (const int*)domains;
#pragma unroll
        for (int j = 0; j < 8; j++) idx[j] = __ldg(d + row0 + j);
    } else {
        const long long* d = (const long long*)domains;
#pragma unroll
        for (int j = 0; j < 8; j++) idx[j] = (int)__ldg(d + row0 + j);
    }
    const float4* z4 = (const float4*)g_z;
    float4 v[8];
#pragma unroll
    for (int j = 0; j < 8; j++) v[j] = __ldg(z4 + (size_t)idx[j] * 64 + q);
#pragma unroll
    for (int j = 0; j < 8; j++)
        st_cs4(out + (size_t)(row0 + j) * 64 + q, v[j]);
}

// ---------------- launch ---------------------------------------------------
extern "C" void kernel_launch(void* const* d_in, const int* in_sizes, int n_in,
                              void* d_out, int out_size) {
    const float* x   = (const float*)d_in[0];
    const float* sn  = (const float*)d_in[1];
    const void*  dom = d_in[2];
    const float* w   = (const float*)d_in[3];
    const float* b   = (const float*)d_in[4];

    cudaFuncSetAttribute(zgemm_mma_kernel,
                         cudaFuncAttributeMaxDynamicSharedMemorySize,
                         NSTAGES * STAGE_BYTES);

    prep_w_kernel<<<(C_IN * C_OUT + 255) / 256, 256>>>(w);
    prep_a_kernel<<<(N_NODES * 64 + 255) / 256, 256>>>(x, sn);
    detect_dom_kernel<<<1, 256>>>((const long long*)dom);

    zgemm_mma_kernel<<<M_TILES * 2, 256, NSTAGES * STAGE_BYTES>>>(b);

    gather_kernel<<<(D_DOM * K_DOM) / 32, 256>>>(dom, (float4*)d_out);
}

// round 7
// speedup vs baseline: 1.8375x; 1.0777x over previous
#include <cuda_runtime.h>
#include <cuda_bf16.h>
#include <cstdint>

#define N_NODES 50000
#define C_IN    256
#define C_OUT   256
#define D_DOM   25000
#define K_DOM   16
#define N_ROWS  (D_DOM * K_DOM)      // 400000 output rows

#define BM      128
#define BN      128
#define NCHUNK  16            // 16 K-chunks of 16 = K 256
#define NSTAGES 4
#define STAGE_BYTES 16384     // Ahi/Alo/Bhi/Blo, 4KB each
#define SM_A_HI 0
#define SM_A_LO 4096
#define SM_B_HI 8192
#define SM_B_LO 12288
#define M_TILES ((N_NODES + BM - 1) / BM)    // 391

// ---------------- scratch (static device globals; no cudaMalloc) -----------
__device__ __align__(16) __nv_bfloat16  g_wt_hi[C_OUT * C_IN];
__device__ __align__(16) __nv_bfloat16  g_wt_lo[C_OUT * C_IN];
__device__ __align__(16) __nv_bfloat16  g_a_hi[(size_t)N_NODES * C_IN]; // 25.6MB
__device__ __align__(16) __nv_bfloat16  g_a_lo[(size_t)N_NODES * C_IN]; // 25.6MB
__device__ int g_dom_is32;
// inverse map (node -> output rows), CSR with atomic block allocation
__device__ unsigned g_cnt[N_NODES];
__device__ unsigned g_off[N_NODES];
__device__ unsigned g_cur[N_NODES];
__device__ unsigned g_pos[N_ROWS];
__device__ unsigned g_total;

// ---------------- helpers ---------------------------------------------------
__device__ __forceinline__ uint32_t smem_u32(const void* p) {
    uint32_t a;
    asm("{ .reg .u64 t; cvta.to.shared.u64 t, %1; cvt.u32.u64 %0, t; }"
        : "=r"(a) : "l"(p));
    return a;
}

__device__ __forceinline__ void cp16(uint32_t dst, const void* src, int sz) {
    asm volatile("cp.async.cg.shared.global [%0], [%1], 16, %2;"
                 :: "r"(dst), "l"(src), "r"(sz) : "memory");
}

#define CP_COMMIT() asm volatile("cp.async.commit_group;" ::: "memory")
#define CP_WAIT2()  asm volatile("cp.async.wait_group 2;" ::: "memory")
#define CP_WAIT0()  asm volatile("cp.async.wait_group 0;" ::: "memory")

#define LDM4(r0, r1, r2, r3, addr) \
    asm volatile("ldmatrix.sync.aligned.m8n8.x4.shared.b16 {%0,%1,%2,%3}, [%4];" \
                 : "=r"(r0), "=r"(r1), "=r"(r2), "=r"(r3) : "r"(addr))

#define MMA16816(d, a, b) \
    asm volatile("mma.sync.aligned.m16n8k16.row.col.f32.bf16.bf16.f32 " \
                 "{%0,%1,%2,%3}, {%4,%5,%6,%7}, {%8,%9}, {%0,%1,%2,%3};" \
                 : "+f"((d)[0]), "+f"((d)[1]), "+f"((d)[2]), "+f"((d)[3]) \
                 : "r"((a)[0]), "r"((a)[1]), "r"((a)[2]), "r"((a)[3]), \
                   "r"((b)[0]), "r"((b)[1]))

__device__ __forceinline__ uint32_t pack_bf16(float a, float b) {
    __nv_bfloat16 ha = __float2bfloat16(a);
    __nv_bfloat16 hb = __float2bfloat16(b);
    return ((uint32_t)__bfloat16_as_ushort(hb) << 16) | __bfloat16_as_ushort(ha);
}

__device__ __forceinline__ void st_cs4(float4* p, float4 v) {
    asm volatile("st.global.cs.v4.f32 [%0], {%1,%2,%3,%4};"
                 :: "l"(p), "f"(v.x), "f"(v.y), "f"(v.z), "f"(v.w) : "memory");
}

__device__ __forceinline__ int load_dom(const void* domains, int r) {
    if (g_dom_is32) return __ldg((const int*)domains + r);
    return (int)__ldg((const long long*)domains + r);
}

// ---------------- kernel: weff^T = (w0+w1)^T, split hi/lo bf16 -------------
__global__ void prep_w_kernel(const float* __restrict__ w) {
    int i = blockIdx.x * blockDim.x + threadIdx.x;
    if (i < C_IN * C_OUT) {
        int n = i & (C_OUT - 1);
        int k = i >> 8;
        float v = w[k * C_OUT + n] + w[(k + C_IN) * C_OUT + n];
        __nv_bfloat16 h = __float2bfloat16(v);
        g_wt_hi[n * C_IN + k] = h;
        g_wt_lo[n * C_IN + k] = __float2bfloat16(v - __bfloat162float(h));
    }
}

// ---------------- kernel: A = x * sn, split hi/lo bf16 ---------------------
__global__ __launch_bounds__(256)
void prep_a_kernel(const float* __restrict__ x, const float* __restrict__ sn) {
    int idx = blockIdx.x * 256 + threadIdx.x;        // 0 .. N*64-1
    if (idx >= N_NODES * 64) return;
    int row = idx >> 6;
    int c4  = idx & 63;
    float s = __ldg(sn + row);
    float4 v = *(const float4*)(x + (size_t)row * C_IN + c4 * 4);
    v.x *= s; v.y *= s; v.z *= s; v.w *= s;
    __nv_bfloat16 h0 = __float2bfloat16(v.x);
    __nv_bfloat16 h1 = __float2bfloat16(v.y);
    __nv_bfloat16 h2 = __float2bfloat16(v.z);
    __nv_bfloat16 h3 = __float2bfloat16(v.w);
    uint2 hi, lo;
    hi.x = ((uint32_t)__bfloat16_as_ushort(h1) << 16) | __bfloat16_as_ushort(h0);
    hi.y = ((uint32_t)__bfloat16_as_ushort(h3) << 16) | __bfloat16_as_ushort(h2);
    lo.x = pack_bf16(v.x - __bfloat162float(h0), v.y - __bfloat162float(h1));
    lo.y = pack_bf16(v.z - __bfloat162float(h2), v.w - __bfloat162float(h3));
    *(uint2*)(g_a_hi + (size_t)row * C_IN + c4 * 4) = hi;
    *(uint2*)(g_a_lo + (size_t)row * C_IN + c4 * 4) = lo;
}

// ---------------- kernel: detect domains dtype -----------------------------
__global__ void detect_dom_kernel(const long long* __restrict__ dom) {
    int bad = 0;
    for (int i = threadIdx.x; i < 2048; i += 256) {
        long long v = dom[i];
        if (v < 0 || v >= (long long)N_NODES) bad = 1;
    }
    bad = __syncthreads_or(bad);
    if (threadIdx.x == 0) g_dom_is32 = bad;
}

// ---------------- inverse-map build ----------------------------------------
__global__ void k_zero(void) {
    int i = blockIdx.x * 256 + threadIdx.x;
    if (i < N_NODES) g_cnt[i] = 0;
    if (i == 0) g_total = 0;
}

__global__ void k_hist(const void* __restrict__ domains) {
    int r = blockIdx.x * 256 + threadIdx.x;
    if (r < N_ROWS) atomicAdd(&g_cnt[load_dom(domains, r)], 1u);
}

// Per-block scan of counts + atomic base allocation. Offsets are grouped per
// node (CSR) but block bases come from an atomic counter: ordering varies
// across replays, OUTPUT does not (each out row written once, value fixed).
__global__ __launch_bounds__(1024)
void k_allocscan(void) {
    const int tid = threadIdx.x;
    const int i = blockIdx.x * 1024 + tid;
    unsigned v = (i < N_NODES) ? g_cnt[i] : 0;
    unsigned incl = v;
#pragma unroll
    for (int o = 1; o < 32; o <<= 1) {
        unsigned t = __shfl_up_sync(0xFFFFFFFFu, incl, o);
        if ((tid & 31) >= o) incl += t;
    }
    __shared__ unsigned wsum[32];
    __shared__ unsigned sbase;
    if ((tid & 31) == 31) wsum[tid >> 5] = incl;
    __syncthreads();
    if (tid < 32) {
        unsigned s = wsum[tid];
        unsigned is = s;
#pragma unroll
        for (int o = 1; o < 32; o <<= 1) {
            unsigned t = __shfl_up_sync(0xFFFFFFFFu, is, o);
            if (tid >= o) is += t;
        }
        wsum[tid] = is - s;                 // exclusive warp-prefix
        if (tid == 31) sbase = atomicAdd(&g_total, is);   // block total
    }
    __syncthreads();
    unsigned excl = sbase + wsum[tid >> 5] + (incl - v);
    if (i < N_NODES) { g_off[i] = excl; g_cur[i] = excl; }
}

__global__ void k_fill(const void* __restrict__ domains) {
    int r = blockIdx.x * 256 + threadIdx.x;
    if (r < N_ROWS) {
        int i = load_dom(domains, r);
        unsigned p = atomicAdd(&g_cur[i], 1u);
        g_pos[p] = (unsigned)r;
    }
}

// ---------------- fused GEMM + scatter -------------------------------------
// z-tile = A @ weff + b computed in registers; epilogue stages the 128x128
// f32 tile in smem, then scatters each node row to all its output rows.
extern __shared__ char dsm[];

__global__ __launch_bounds__(256)
void zgemm_scatter_kernel(const float* __restrict__ bias,
                          float4* __restrict__ out) {
    const int tid = threadIdx.x;
    const int m0 = (blockIdx.x >> 1) * BM;
    const int n0 = (blockIdx.x & 1) * BN;
    const uint32_t sb = smem_u32(dsm);

    // --- copy-role mapping -------------------------------------------------
    const int crow = tid >> 1;
    const int cseg = tid & 1;
    const int gmA  = m0 + crow;
    const int szA  = (gmA < N_NODES) ? 16 : 0;
    const char* srcAhi = (const char*)(g_a_hi + (size_t)gmA * C_IN + cseg * 8);
    const char* srcAlo = (const char*)(g_a_lo + (size_t)gmA * C_IN + cseg * 8);
    const char* srcBhi = (const char*)(g_wt_hi + (size_t)(n0 + crow) * C_IN + cseg * 8);
    const char* srcBlo = (const char*)(g_wt_lo + (size_t)(n0 + crow) * C_IN + cseg * 8);
    const uint32_t doff = crow * 32 + (uint32_t)(cseg ^ ((crow >> 2) & 1)) * 16;

#define ISSUE_COPY(s, kc) do {                                   \
        uint32_t _sbase = sb + (uint32_t)(s) * STAGE_BYTES;      \
        int _go = (kc) * 32;                                     \
        cp16(_sbase + SM_A_HI + doff, srcAhi + _go, szA);        \
        cp16(_sbase + SM_A_LO + doff, srcAlo + _go, szA);        \
        cp16(_sbase + SM_B_HI + doff, srcBhi + _go, 16);         \
        cp16(_sbase + SM_B_LO + doff, srcBlo + _go, 16);         \
    } while (0)

    ISSUE_COPY(0, 0); CP_COMMIT();
    ISSUE_COPY(1, 1); CP_COMMIT();
    ISSUE_COPY(2, 2); CP_COMMIT();

    // --- compute-role mapping ----------------------------------------------
    const int lane = tid & 31;
    const int wid  = tid >> 5;
    const int wm   = wid & 1;
    const int wn   = wid >> 1;
    const int lrow  = lane & 15;
    const int lhalf = lane >> 4;
    const int swz = (lrow >> 2) & 1;
    const uint32_t a_off = (uint32_t)(wm * 64 + lrow) * 32 + (uint32_t)(lhalf ^ swz) * 16;
    const uint32_t b_off = (uint32_t)(wn * 32 + lrow) * 32 + (uint32_t)(lhalf ^ swz) * 16;

    float acc[4][4][4];
#pragma unroll
    for (int mt = 0; mt < 4; mt++)
#pragma unroll
        for (int nt = 0; nt < 4; nt++)
#pragma unroll
            for (int j = 0; j < 4; j++) acc[mt][nt][j] = 0.0f;

    for (int kc = 0; kc < NCHUNK; kc++) {
        CP_WAIT2();
        __syncthreads();
        int pf = kc + NSTAGES - 1;
        if (pf < NCHUNK) ISSUE_COPY(pf & (NSTAGES - 1), pf);
        CP_COMMIT();

        const uint32_t st = sb + (uint32_t)(kc & (NSTAGES - 1)) * STAGE_BYTES;

        uint32_t ah[4][4], bh[4][2], bl[4][2];
#pragma unroll
        for (int mt = 0; mt < 4; mt++)
            LDM4(ah[mt][0], ah[mt][1], ah[mt][2], ah[mt][3],
                 st + SM_A_HI + a_off + mt * 512);
#pragma unroll
        for (int ntp = 0; ntp < 2; ntp++) {
            uint32_t r0, r1, r2, r3;
            LDM4(r0, r1, r2, r3, st + SM_B_HI + b_off + ntp * 512);
            bh[ntp * 2][0] = r0; bh[ntp * 2][1] = r2;
            bh[ntp * 2 + 1][0] = r1; bh[ntp * 2 + 1][1] = r3;
            LDM4(r0, r1, r2, r3, st + SM_B_LO + b_off + ntp * 512);
            bl[ntp * 2][0] = r0; bl[ntp * 2][1] = r2;
            bl[ntp * 2 + 1][0] = r1; bl[ntp * 2 + 1][1] = r3;
        }
#pragma unroll
        for (int mt = 0; mt < 4; mt++)
#pragma unroll
            for (int nt = 0; nt < 4; nt++) {
                MMA16816(acc[mt][nt], ah[mt], bh[nt]);
                MMA16816(acc[mt][nt], ah[mt], bl[nt]);
            }
#pragma unroll
        for (int mt = 0; mt < 4; mt++)
            LDM4(ah[mt][0], ah[mt][1], ah[mt][2], ah[mt][3],
                 st + SM_A_LO + a_off + mt * 512);
#pragma unroll
        for (int mt = 0; mt < 4; mt++)
#pragma unroll
            for (int nt = 0; nt < 4; nt++)
                MMA16816(acc[mt][nt], ah[mt], bh[nt]);
    }

    // --- epilogue 1: stage tile (+bias) into smem as f32[128][128] ---------
    CP_WAIT0();
    __syncthreads();                       // pipeline smem now reusable
    float* stile = (float*)dsm;            // 64KB = exactly 128*128 f32
    const int erow = lane >> 2;
    const int ecol = (lane & 3) * 2;
#pragma unroll
    for (int nt = 0; nt < 4; nt++) {
        int nl = wn * 32 + nt * 8 + ecol;
        float b0v = bias[n0 + nl];
        float b1v = bias[n0 + nl + 1];
#pragma unroll
        for (int mt = 0; mt < 4; mt++) {
            int ml = wm * 64 + mt * 16 + erow;
            stile[ml * 128 + nl]           = acc[mt][nt][0] + b0v;
            stile[ml * 128 + nl + 1]       = acc[mt][nt][1] + b1v;
            stile[(ml + 8) * 128 + nl]     = acc[mt][nt][2] + b0v;
            stile[(ml + 8) * 128 + nl + 1] = acc[mt][nt][3] + b1v;
        }
    }
    __syncthreads();

    // --- epilogue 2: scatter each node row to its output rows --------------
    // warp w owns local rows [w*16, w*16+16); one float4/lane = 512B/row/dup.
    const int wrow0 = wid * 16;
#pragma unroll 1
    for (int rr = 0; rr < 16; rr++) {
        int node = m0 + wrow0 + rr;
        if (node >= N_NODES) break;
        unsigned start = __ldg(&g_off[node]);
        unsigned cnt   = __ldg(&g_cnt[node]);
        float4 v = *(float4*)(stile + (wrow0 + rr) * 128 + lane * 4);
#pragma unroll 1
        for (unsigned p = 0; p < cnt; p++) {
            unsigned r = __ldg(&g_pos[start + p]);
            st_cs4(out + (size_t)r * 64 + (n0 >> 2) + lane, v);
        }
    }
#undef ISSUE_COPY
}

// ---------------- launch ---------------------------------------------------
extern "C" void kernel_launch(void* const* d_in, const int* in_sizes, int n_in,
                              void* d_out, int out_size) {
    const float* x   = (const float*)d_in[0];
    const float* sn  = (const float*)d_in[1];
    const void*  dom = d_in[2];
    const float* w   = (const float*)d_in[3];
    const float* b   = (const float*)d_in[4];

    cudaFuncSetAttribute(zgemm_scatter_kernel,
                         cudaFuncAttributeMaxDynamicSharedMemorySize,
                         NSTAGES * STAGE_BYTES);

    detect_dom_kernel<<<1, 256>>>((const long long*)dom);
    prep_w_kernel<<<(C_IN * C_OUT + 255) / 256, 256>>>(w);
    prep_a_kernel<<<(N_NODES * 64 + 255) / 256, 256>>>(x, sn);

    k_zero<<<(N_NODES + 255) / 256, 256>>>();
    k_hist<<<(N_ROWS + 255) / 256, 256>>>(dom);
    k_allocscan<<<(N_NODES + 1023) / 1024, 1024>>>();
    k_fill<<<(N_ROWS + 255) / 256, 256>>>(dom);

    zgemm_scatter_kernel<<<M_TILES * 2, 256, NSTAGES * STAGE_BYTES>>>(
        b, (float4*)d_out);
}